// round 2
// baseline (speedup 1.0000x reference)
#include <cuda_runtime.h>
#include <math.h>

#define NB      64
#define NC      640
#define HW      784      // 28*28
#define S2      196      // 14*14
#define NHEADS  8
#define DH      64
#define INNER   512      // NHEADS*DH
#define EPSF    1e-5f
#define ATTN_SCALE 0.125f   // 64^-0.5

// ---------------- scratch (device globals; no allocation) ----------------
__device__ float g_dwq [NB * NC * HW];     // dwconv(s1)+BN  -> GEMM A for q
__device__ float g_dwkv[NB * NC * S2];     // dwconv(s2)+BN  -> GEMM A for kv
__device__ float g_q   [NB * INNER * HW];  // q  [b][h*64+d][pos]
__device__ float g_kv  [NB * 2 * INNER * S2];
__device__ float g_res [NB * DH * HW];     // residual [b][d][pos]

// =====================================================================
// Fused depthwise conv (stride1 + stride2) + BN, per (b,c) block.
// =====================================================================
__global__ void __launch_bounds__(256)
dwconv_fused(const float* __restrict__ x,
             const float* __restrict__ wq, const float* __restrict__ wkv,
             const float* __restrict__ qg, const float* __restrict__ qb,
             const float* __restrict__ qm, const float* __restrict__ qvv,
             const float* __restrict__ kg, const float* __restrict__ kb,
             const float* __restrict__ km, const float* __restrict__ kvv)
{
    const int bc = blockIdx.x;          // b*NC + c
    const int c  = bc % NC;
    __shared__ float xs[30 * 30];       // zero-padded tile
    const int tid = threadIdx.x;

    for (int i = tid; i < 900; i += 256) xs[i] = 0.f;
    __syncthreads();
    const float* xp = x + (size_t)bc * HW;
    for (int p = tid; p < HW; p += 256) {
        int yy = p / 28, xx = p % 28;
        xs[(yy + 1) * 30 + xx + 1] = xp[p];
    }
    __syncthreads();

    float wq9[9], wk9[9];
#pragma unroll
    for (int i = 0; i < 9; i++) { wq9[i] = wq[c * 9 + i]; wk9[i] = wkv[c * 9 + i]; }

    const float sq  = qg[c] * rsqrtf(qvv[c] + EPSF);
    const float bq  = qb[c] - qm[c] * sq;
    const float skv = kg[c] * rsqrtf(kvv[c] + EPSF);
    const float bkv = kb[c] - km[c] * skv;

    // stride-1 output (28x28)
    for (int p = tid; p < HW; p += 256) {
        int oy = p / 28, ox = p % 28;
        const float* s = &xs[oy * 30 + ox];
        float acc = s[0]*wq9[0] + s[1]*wq9[1] + s[2]*wq9[2]
                  + s[30]*wq9[3] + s[31]*wq9[4] + s[32]*wq9[5]
                  + s[60]*wq9[6] + s[61]*wq9[7] + s[62]*wq9[8];
        g_dwq[(size_t)bc * HW + p] = acc * sq + bq;
    }
    // stride-2 output (14x14)
    for (int p = tid; p < S2; p += 256) {
        int oy = p / 14, ox = p % 14;
        const float* s = &xs[(oy * 2) * 30 + (ox * 2)];
        float acc = s[0]*wk9[0] + s[1]*wk9[1] + s[2]*wk9[2]
                  + s[30]*wk9[3] + s[31]*wk9[4] + s[32]*wk9[5]
                  + s[60]*wk9[6] + s[61]*wk9[7] + s[62]*wk9[8];
        g_dwkv[(size_t)bc * S2 + p] = acc * skv + bkv;
    }
}

// =====================================================================
// Generic batched GEMM:  C[b] (MxN) = Wm (MxK) * A[b] (KxN)
// optional per-row BN epilogue. BM=BN=64, BK=16, 256 thr, 4x4/thread.
// =====================================================================
__global__ void __launch_bounds__(256)
gemm_bn(const float* __restrict__ Wm, const float* __restrict__ A,
        float* __restrict__ Cc, int M, int N, int K,
        const float* __restrict__ bg, const float* __restrict__ bb,
        const float* __restrict__ bm, const float* __restrict__ bv)
{
    __shared__ __align__(16) float Ws[16 * 68];
    __shared__ __align__(16) float As[16 * 68];

    const int tid = threadIdx.x;
    const int tx = tid & 15, ty = tid >> 4;
    const int n0 = blockIdx.x * 64;
    const int m0 = blockIdx.y * 64;
    const float* Ab = A  + (size_t)blockIdx.z * K * N;
    float*       Cb = Cc + (size_t)blockIdx.z * M * N;

    const int wm = tid >> 2, wk = (tid & 3) << 2;   // W loader: row wm, 4 k's
    const int ak = tid >> 4, an = (tid & 15) << 2;  // A loader: row ak, 4 n's

    float acc[4][4];
#pragma unroll
    for (int i = 0; i < 4; i++)
#pragma unroll
        for (int j = 0; j < 4; j++) acc[i][j] = 0.f;

    for (int k0 = 0; k0 < K; k0 += 16) {
        float4 wv = *(const float4*)&Wm[(size_t)(m0 + wm) * K + k0 + wk];
        Ws[(wk + 0) * 68 + wm] = wv.x;
        Ws[(wk + 1) * 68 + wm] = wv.y;
        Ws[(wk + 2) * 68 + wm] = wv.z;
        Ws[(wk + 3) * 68 + wm] = wv.w;
        float4 av = make_float4(0.f, 0.f, 0.f, 0.f);
        if (n0 + an < N)
            av = *(const float4*)&Ab[(size_t)(k0 + ak) * N + n0 + an];
        *(float4*)&As[ak * 68 + an] = av;
        __syncthreads();
#pragma unroll
        for (int kk = 0; kk < 16; kk++) {
            float4 a4 = *(const float4*)&As[kk * 68 + (tx << 2)];
            float4 w4 = *(const float4*)&Ws[kk * 68 + (ty << 2)];
            acc[0][0] += w4.x * a4.x; acc[0][1] += w4.x * a4.y;
            acc[0][2] += w4.x * a4.z; acc[0][3] += w4.x * a4.w;
            acc[1][0] += w4.y * a4.x; acc[1][1] += w4.y * a4.y;
            acc[1][2] += w4.y * a4.z; acc[1][3] += w4.y * a4.w;
            acc[2][0] += w4.z * a4.x; acc[2][1] += w4.z * a4.y;
            acc[2][2] += w4.z * a4.z; acc[2][3] += w4.z * a4.w;
            acc[3][0] += w4.w * a4.x; acc[3][1] += w4.w * a4.y;
            acc[3][2] += w4.w * a4.z; acc[3][3] += w4.w * a4.w;
        }
        __syncthreads();
    }

    const bool has_bn = (bg != nullptr);
#pragma unroll
    for (int i = 0; i < 4; i++) {
        int row = m0 + ty * 4 + i;
        float sc = 1.f, bi = 0.f;
        if (has_bn) { sc = bg[row] * rsqrtf(bv[row] + EPSF); bi = bb[row] - bm[row] * sc; }
#pragma unroll
        for (int j = 0; j < 4; j++) {
            int col = n0 + tx * 4 + j;
            if (col < N) Cb[(size_t)row * N + col] = acc[i][j] * sc + bi;
        }
    }
}

// =====================================================================
// Fused attention + residual + LayerNorm + spatial mean pool.
// One block per (b,h). k,v staged in smem; thread-per-query-row.
// =====================================================================
__global__ void __launch_bounds__(256, 1)
attn_kernel(const float* __restrict__ lnw, const float* __restrict__ lnbp,
            float* __restrict__ out)
{
    const int bh = blockIdx.x;      // b*8 + h
    const int b  = bh >> 3;
    const int h  = bh & 7;

    extern __shared__ __align__(16) float sm[];
    float* ksm  = sm;                  // [196][68]
    float* vsm  = ksm + S2 * 68;       // [196][68]
    float* lng  = vsm + S2 * 68;       // [64]
    float* lnb  = lng + 64;            // [64]
    float* redw = lnb + 64;            // [8][64]

    const int tid  = threadIdx.x;
    const int lane = tid & 31, warp = tid >> 5;

    for (int idx = tid; idx < S2 * DH; idx += 256) {
        int d = idx / S2, j = idx % S2;
        ksm[j * 68 + d] = g_kv[((size_t)b * 1024 + h * 64 + d) * S2 + j];
        vsm[j * 68 + d] = g_kv[((size_t)b * 1024 + 512 + h * 64 + d) * S2 + j];
    }
    if (tid < 64) { lng[tid] = lnw[h * 64 + tid]; lnb[tid] = lnbp[h * 64 + tid]; }
    for (int i = tid; i < 512; i += 256) redw[i] = 0.f;
    __syncthreads();

    for (int it = 0; it < 4; it++) {
        const int row = it * 256 + tid;
        const bool act = row < HW;
        float acc[64];
#pragma unroll
        for (int d = 0; d < 64; d++) acc[d] = 0.f;

        if (act) {
            float q[64];
#pragma unroll
            for (int d = 0; d < 64; d++)
                q[d] = g_q[((size_t)b * INNER + h * 64 + d) * HW + row];
            float mval = -1e30f, l = 0.f;

            for (int j = 0; j < S2; j++) {
                const float* kr = &ksm[j * 68];
                float s = 0.f;
#pragma unroll
                for (int d4 = 0; d4 < 16; d4++) {
                    float4 k4 = *(const float4*)&kr[d4 * 4];
                    s += q[d4*4+0]*k4.x + q[d4*4+1]*k4.y
                       + q[d4*4+2]*k4.z + q[d4*4+3]*k4.w;
                }
                s *= ATTN_SCALE;
                if (s > mval) {
                    float corr = __expf(mval - s);
                    l *= corr;
#pragma unroll
                    for (int d = 0; d < 64; d++) acc[d] *= corr;
                    mval = s;
                }
                float p = __expf(s - mval);
                l += p;
                const float* vr = &vsm[j * 68];
#pragma unroll
                for (int d4 = 0; d4 < 16; d4++) {
                    float4 v4 = *(const float4*)&vr[d4 * 4];
                    acc[d4*4+0] += p * v4.x; acc[d4*4+1] += p * v4.y;
                    acc[d4*4+2] += p * v4.z; acc[d4*4+3] += p * v4.w;
                }
            }

            // normalize + residual + LayerNorm, in place on acc
            const float linv = 1.f / l;
            float mean = 0.f;
#pragma unroll
            for (int d = 0; d < 64; d++) {
                float o = acc[d] * linv + g_res[((size_t)b * DH + d) * HW + row];
                acc[d] = o; mean += o;
            }
            mean *= (1.f / 64.f);
            float var = 0.f;
#pragma unroll
            for (int d = 0; d < 64; d++) { float t = acc[d] - mean; var += t * t; }
            var *= (1.f / 64.f);
            const float inv = 1.f / (sqrtf(var) + EPSF);
#pragma unroll
            for (int d = 0; d < 64; d++)
                acc[d] = (acc[d] - mean) * inv * lng[d] + lnb[d];
        }

        // warp butterfly: sum over the 32 rows handled by this warp
#pragma unroll
        for (int d = 0; d < 64; d++) {
            acc[d] += __shfl_xor_sync(0xffffffffu, acc[d], 16);
            acc[d] += __shfl_xor_sync(0xffffffffu, acc[d], 8);
            acc[d] += __shfl_xor_sync(0xffffffffu, acc[d], 4);
            acc[d] += __shfl_xor_sync(0xffffffffu, acc[d], 2);
            acc[d] += __shfl_xor_sync(0xffffffffu, acc[d], 1);
        }
        if (lane == 0) {
#pragma unroll
            for (int d = 0; d < 64; d++) redw[warp * 64 + d] += acc[d];
        }
        __syncthreads();
    }

    if (tid < 64) {
        float t = 0.f;
#pragma unroll
        for (int w = 0; w < 8; w++) t += redw[w * 64 + tid];
        out[(size_t)bh * 64 + tid] = t * (1.f / 784.f);
    }
}

// =====================================================================
extern "C" void kernel_launch(void* const* d_in, const int* in_sizes, int n_in,
                              void* d_out, int out_size)
{
    const float* x      = (const float*)d_in[0];
    const float* w_dwq  = (const float*)d_in[1];
    const float* w_pwq  = (const float*)d_in[2];
    const float* w_dwkv = (const float*)d_in[3];
    const float* w_pwkv = (const float*)d_in[4];
    const float* w_ds   = (const float*)d_in[5];
    const float* ln_g   = (const float*)d_in[6];
    const float* ln_b   = (const float*)d_in[7];
    const float* bnq_g  = (const float*)d_in[8];
    const float* bnq_b  = (const float*)d_in[9];
    const float* bnq_m  = (const float*)d_in[10];
    const float* bnq_v  = (const float*)d_in[11];
    const float* bnkv_g = (const float*)d_in[12];
    const float* bnkv_b = (const float*)d_in[13];
    const float* bnkv_m = (const float*)d_in[14];
    const float* bnkv_v = (const float*)d_in[15];
    const float* bnds_g = (const float*)d_in[16];
    const float* bnds_b = (const float*)d_in[17];
    const float* bnds_m = (const float*)d_in[18];
    const float* bnds_v = (const float*)d_in[19];
    float* out = (float*)d_out;

    float *p_dwq, *p_dwkv, *p_q, *p_kv, *p_res;
    cudaGetSymbolAddress((void**)&p_dwq,  g_dwq);
    cudaGetSymbolAddress((void**)&p_dwkv, g_dwkv);
    cudaGetSymbolAddress((void**)&p_q,    g_q);
    cudaGetSymbolAddress((void**)&p_kv,   g_kv);
    cudaGetSymbolAddress((void**)&p_res,  g_res);

    const int smem_bytes = (2 * S2 * 68 + 64 + 64 + 512) * (int)sizeof(float);
    static bool attr_done = false;
    if (!attr_done) {
        cudaFuncSetAttribute(attn_kernel,
                             cudaFuncAttributeMaxDynamicSharedMemorySize, smem_bytes);
        attr_done = true;
    }

    // 1) fused depthwise convs + BN
    dwconv_fused<<<NB * NC, 256>>>(x, w_dwq, w_dwkv,
                                   bnq_g, bnq_b, bnq_m, bnq_v,
                                   bnkv_g, bnkv_b, bnkv_m, bnkv_v);

    // 2) residual pointwise conv + BN (reads x directly)
    gemm_bn<<<dim3(13, 1, NB), 256>>>(w_ds, x, p_res, DH, HW, NC,
                                      bnds_g, bnds_b, bnds_m, bnds_v);

    // 3) q projection
    gemm_bn<<<dim3(13, 8, NB), 256>>>(w_pwq, p_dwq, p_q, INNER, HW, NC,
                                      nullptr, nullptr, nullptr, nullptr);

    // 4) kv projection
    gemm_bn<<<dim3(4, 16, NB), 256>>>(w_pwkv, p_dwkv, p_kv, 2 * INNER, S2, NC,
                                      nullptr, nullptr, nullptr, nullptr);

    // 5) fused attention + residual + LN + mean pool
    attn_kernel<<<NB * NHEADS, 256, smem_bytes>>>(ln_g, ln_b, out);
}

// round 5
// speedup vs baseline: 1.7053x; 1.7053x over previous
#include <cuda_runtime.h>
#include <math.h>
#include <stdint.h>

#define NB      64
#define NC      640      // K of all GEMMs
#define HW      784      // 28*28
#define S2      196      // 14*14
#define NHEADS  8
#define DH      64
#define INNER   512      // NHEADS*DH
#define EPSF    1e-5f
#define ATTN_SCALE 0.125f

// ---------------- scratch (device globals; no allocation) ----------------
__device__ float g_dwq [NB * NC * HW];       // dwconv(s1)+BN (tf32-rounded)
__device__ float g_dwkv[NB * NC * S2];       // dwconv(s2)+BN (tf32-rounded)
__device__ float g_q   [NB * INNER * HW];    // q  [b][h*64+d][pos]
__device__ float g_kv  [NB * 2 * INNER * S2];
__device__ float g_res [NB * DH * HW];       // residual [b][d][pos]
__device__ float g_wq  [NC * 512];           // w_pwq^T  [k][m], tf32
__device__ float g_wkv [NC * 1024];          // w_pwkv^T [k][m], tf32
__device__ float g_wds [NC * 128];           // w_ds^T   [k][m], tf32, zero-padded to 128

// ---------------- helpers ----------------
__device__ __forceinline__ float to_tf32(float v) {
    uint32_t r;
    asm("cvt.rna.tf32.f32 %0, %1;" : "=r"(r) : "f"(v));
    return __uint_as_float(r);
}

__device__ __forceinline__ void cp16(uint32_t dst, const void* src, int src_bytes) {
    asm volatile("cp.async.cg.shared.global [%0], [%1], 16, %2;\n"
                 :: "r"(dst), "l"(src), "r"(src_bytes));
}

__device__ __forceinline__ void mma_tf32(float* c, const uint32_t* a, const uint32_t* b) {
    asm volatile(
        "mma.sync.aligned.m16n8k8.row.col.f32.tf32.tf32.f32 "
        "{%0,%1,%2,%3}, {%4,%5,%6,%7}, {%8,%9}, {%0,%1,%2,%3};\n"
        : "+f"(c[0]), "+f"(c[1]), "+f"(c[2]), "+f"(c[3])
        : "r"(a[0]), "r"(a[1]), "r"(a[2]), "r"(a[3]), "r"(b[0]), "r"(b[1]));
}

// =====================================================================
// Weight transpose + tf32 round:  W[M,K] row-major -> out[K][Mpad]
// =====================================================================
__global__ void __launch_bounds__(256)
prep_w(const float* __restrict__ W, float* __restrict__ outp,
       int M, int K, int Mpad)
{
    int idx = blockIdx.x * 256 + threadIdx.x;
    if (idx >= K * Mpad) return;
    int k = idx / Mpad, m = idx - k * Mpad;
    float v = (m < M) ? W[(size_t)m * K + k] : 0.f;
    outp[idx] = to_tf32(v);
}

// =====================================================================
// Fused depthwise conv (stride1 + stride2) + BN, per (b,c) block.
// Outputs tf32-rounded (feeds the tensor-core GEMMs).
// =====================================================================
__global__ void __launch_bounds__(256)
dwconv_fused(const float* __restrict__ x,
             const float* __restrict__ wq, const float* __restrict__ wkv,
             const float* __restrict__ qg, const float* __restrict__ qb,
             const float* __restrict__ qm, const float* __restrict__ qvv,
             const float* __restrict__ kg, const float* __restrict__ kb,
             const float* __restrict__ km, const float* __restrict__ kvv)
{
    const int bc = blockIdx.x;
    const int c  = bc % NC;
    __shared__ float xs[30 * 30];
    const int tid = threadIdx.x;

    for (int i = tid; i < 900; i += 256) xs[i] = 0.f;
    __syncthreads();
    const float* xp = x + (size_t)bc * HW;
    for (int p = tid; p < HW; p += 256) {
        int yy = p / 28, xx = p % 28;
        xs[(yy + 1) * 30 + xx + 1] = xp[p];
    }
    __syncthreads();

    float wq9[9], wk9[9];
#pragma unroll
    for (int i = 0; i < 9; i++) { wq9[i] = wq[c * 9 + i]; wk9[i] = wkv[c * 9 + i]; }

    const float sq  = qg[c] * rsqrtf(qvv[c] + EPSF);
    const float bq  = qb[c] - qm[c] * sq;
    const float skv = kg[c] * rsqrtf(kvv[c] + EPSF);
    const float bkv = kb[c] - km[c] * skv;

    for (int p = tid; p < HW; p += 256) {
        int oy = p / 28, ox = p % 28;
        const float* s = &xs[oy * 30 + ox];
        float acc = s[0]*wq9[0] + s[1]*wq9[1] + s[2]*wq9[2]
                  + s[30]*wq9[3] + s[31]*wq9[4] + s[32]*wq9[5]
                  + s[60]*wq9[6] + s[61]*wq9[7] + s[62]*wq9[8];
        g_dwq[(size_t)bc * HW + p] = to_tf32(acc * sq + bq);
    }
    for (int p = tid; p < S2; p += 256) {
        int oy = p / 14, ox = p % 14;
        const float* s = &xs[(oy * 2) * 30 + (ox * 2)];
        float acc = s[0]*wk9[0] + s[1]*wk9[1] + s[2]*wk9[2]
                  + s[30]*wk9[3] + s[31]*wk9[4] + s[32]*wk9[5]
                  + s[60]*wk9[6] + s[61]*wk9[7] + s[62]*wk9[8];
        g_dwkv[(size_t)bc * S2 + p] = to_tf32(acc * skv + bkv);
    }
}

// =====================================================================
// tf32 tensor-core GEMM:  C[b](MxN) = wT^T(k-major, [640][Mpad]) * act[b](640xN)
// Block tile 128x64x32, 8 warps of 32x32, 2-stage cp.async pipeline.
// Optional per-row BN epilogue. K fixed = 640.
// Smem: A [32][136] (136%32==8 -> conflict-free frags), B [32][72].
// =====================================================================
#define GEMM_SMEM_FLOATS (2 * (32 * 136 + 32 * 72))
__global__ void __launch_bounds__(256)
gemm_tc(const float* __restrict__ wT, const float* __restrict__ act,
        float* __restrict__ Cc, int Mpad, int M, int N,
        const float* __restrict__ bg, const float* __restrict__ bb,
        const float* __restrict__ bm, const float* __restrict__ bv)
{
    extern __shared__ float sm[];
    const int tid  = threadIdx.x;
    const int lane = tid & 31, warp = tid >> 5;
    const int wm = (warp >> 1) * 32;   // 0,32,64,96
    const int wn = (warp & 1) * 32;    // 0,32
    const int n0 = blockIdx.x * 64;
    const int m0 = blockIdx.y * 128;
    const float* Ab = act + (size_t)blockIdx.z * NC * N;
    float*       Cb = Cc  + (size_t)blockIdx.z * (size_t)M * N;

    float acc[2][4][4];
#pragma unroll
    for (int i = 0; i < 2; i++)
#pragma unroll
        for (int j = 0; j < 4; j++)
#pragma unroll
            for (int l = 0; l < 4; l++) acc[i][j][l] = 0.f;

    const int a_k = tid >> 5, a_m4 = (tid & 31) * 4;   // A chunks: rows a_k + i*8
    const int b_k = tid >> 4, b_n4 = (tid & 15) * 4;   // B chunks: rows b_k + i*16

    auto load_tile = [&](int k0, int st) {
        float* As = sm + st * (32 * 136 + 32 * 72);
        float* Bs = As + 32 * 136;
#pragma unroll
        for (int i = 0; i < 4; i++) {
            int k = a_k + i * 8;
            uint32_t dst = (uint32_t)__cvta_generic_to_shared(&As[k * 136 + a_m4]);
            cp16(dst, wT + (size_t)(k0 + k) * Mpad + m0 + a_m4, 16);
        }
#pragma unroll
        for (int i = 0; i < 2; i++) {
            int k = b_k + i * 16;
            int col = n0 + b_n4;
            uint32_t dst = (uint32_t)__cvta_generic_to_shared(&Bs[k * 72 + b_n4]);
            cp16(dst, Ab + (size_t)(k0 + k) * N + col, (col < N) ? 16 : 0);
        }
        asm volatile("cp.async.commit_group;\n");
    };

    load_tile(0, 0);
    for (int t = 0; t < 20; t++) {
        const int st = t & 1;
        if (t < 19) {
            load_tile((t + 1) * 32, st ^ 1);
            asm volatile("cp.async.wait_group 1;\n");
        } else {
            asm volatile("cp.async.wait_group 0;\n");
        }
        __syncthreads();
        const float* As = sm + st * (32 * 136 + 32 * 72);
        const float* Bs = As + 32 * 136;
#pragma unroll
        for (int kk = 0; kk < 32; kk += 8) {
            uint32_t af[2][4], bf[4][2];
            const int kq   = kk + (lane & 3);
            const int mrow = wm + (lane >> 2);
            const int ncol = wn + (lane >> 2);
#pragma unroll
            for (int mt = 0; mt < 2; mt++) {
                af[mt][0] = __float_as_uint(As[kq * 136 + mrow + mt * 16]);
                af[mt][1] = __float_as_uint(As[kq * 136 + mrow + mt * 16 + 8]);
                af[mt][2] = __float_as_uint(As[(kq + 4) * 136 + mrow + mt * 16]);
                af[mt][3] = __float_as_uint(As[(kq + 4) * 136 + mrow + mt * 16 + 8]);
            }
#pragma unroll
            for (int nt = 0; nt < 4; nt++) {
                bf[nt][0] = __float_as_uint(Bs[kq * 72 + ncol + nt * 8]);
                bf[nt][1] = __float_as_uint(Bs[(kq + 4) * 72 + ncol + nt * 8]);
            }
#pragma unroll
            for (int mt = 0; mt < 2; mt++)
#pragma unroll
                for (int nt = 0; nt < 4; nt++)
                    mma_tf32(acc[mt][nt], af[mt], bf[nt]);
        }
        __syncthreads();
    }

    const bool has_bn = (bg != nullptr);
#pragma unroll
    for (int mt = 0; mt < 2; mt++) {
#pragma unroll
        for (int half = 0; half < 2; half++) {
            const int m = m0 + wm + mt * 16 + (lane >> 2) + half * 8;
            if (m >= M) continue;
            float sc = 1.f, bi = 0.f;
            if (has_bn) { sc = bg[m] * rsqrtf(bv[m] + EPSF); bi = bb[m] - bm[m] * sc; }
#pragma unroll
            for (int nt = 0; nt < 4; nt++) {
                const int n = n0 + wn + nt * 8 + 2 * (lane & 3);
                if (n < N) {
                    float2 v;
                    v.x = acc[mt][nt][half * 2 + 0] * sc + bi;
                    v.y = acc[mt][nt][half * 2 + 1] * sc + bi;
                    *(float2*)&Cb[(size_t)m * N + n] = v;
                }
            }
        }
    }
}

// =====================================================================
// Fused attention + residual + LayerNorm + spatial mean pool.
// =====================================================================
__global__ void __launch_bounds__(256, 1)
attn_kernel(const float* __restrict__ lnw, const float* __restrict__ lnbp,
            float* __restrict__ out)
{
    const int bh = blockIdx.x;
    const int b  = bh >> 3;
    const int h  = bh & 7;

    extern __shared__ __align__(16) float sm[];
    float* ksm  = sm;                  // [196][68]
    float* vsm  = ksm + S2 * 68;       // [196][68]
    float* lng  = vsm + S2 * 68;
    float* lnb  = lng + 64;
    float* redw = lnb + 64;            // [8][64]

    const int tid  = threadIdx.x;
    const int lane = tid & 31, warp = tid >> 5;

    for (int idx = tid; idx < S2 * DH; idx += 256) {
        int d = idx / S2, j = idx % S2;
        ksm[j * 68 + d] = g_kv[((size_t)b * 1024 + h * 64 + d) * S2 + j];
        vsm[j * 68 + d] = g_kv[((size_t)b * 1024 + 512 + h * 64 + d) * S2 + j];
    }
    if (tid < 64) { lng[tid] = lnw[h * 64 + tid]; lnb[tid] = lnbp[h * 64 + tid]; }
    for (int i = tid; i < 512; i += 256) redw[i] = 0.f;
    __syncthreads();

    for (int it = 0; it < 4; it++) {
        const int row = it * 256 + tid;
        const bool act = row < HW;
        float acc[64];
#pragma unroll
        for (int d = 0; d < 64; d++) acc[d] = 0.f;

        if (act) {
            float q[64];
#pragma unroll
            for (int d = 0; d < 64; d++)
                q[d] = g_q[((size_t)b * INNER + h * 64 + d) * HW + row];
            float mval = -1e30f, l = 0.f;

            for (int j = 0; j < S2; j++) {
                const float* kr = &ksm[j * 68];
                float s = 0.f;
#pragma unroll
                for (int d4 = 0; d4 < 16; d4++) {
                    float4 k4 = *(const float4*)&kr[d4 * 4];
                    s += q[d4*4+0]*k4.x + q[d4*4+1]*k4.y
                       + q[d4*4+2]*k4.z + q[d4*4+3]*k4.w;
                }
                s *= ATTN_SCALE;
                if (s > mval) {
                    float corr = __expf(mval - s);
                    l *= corr;
#pragma unroll
                    for (int d = 0; d < 64; d++) acc[d] *= corr;
                    mval = s;
                }
                float p = __expf(s - mval);
                l += p;
                const float* vr = &vsm[j * 68];
#pragma unroll
                for (int d4 = 0; d4 < 16; d4++) {
                    float4 v4 = *(const float4*)&vr[d4 * 4];
                    acc[d4*4+0] += p * v4.x; acc[d4*4+1] += p * v4.y;
                    acc[d4*4+2] += p * v4.z; acc[d4*4+3] += p * v4.w;
                }
            }

            const float linv = 1.f / l;
            float mean = 0.f;
#pragma unroll
            for (int d = 0; d < 64; d++) {
                float o = acc[d] * linv + g_res[((size_t)b * DH + d) * HW + row];
                acc[d] = o; mean += o;
            }
            mean *= (1.f / 64.f);
            float var = 0.f;
#pragma unroll
            for (int d = 0; d < 64; d++) { float t = acc[d] - mean; var += t * t; }
            var *= (1.f / 64.f);
            const float inv = 1.f / (sqrtf(var) + EPSF);
#pragma unroll
            for (int d = 0; d < 64; d++)
                acc[d] = (acc[d] - mean) * inv * lng[d] + lnb[d];
        }

#pragma unroll
        for (int d = 0; d < 64; d++) {
            acc[d] += __shfl_xor_sync(0xffffffffu, acc[d], 16);
            acc[d] += __shfl_xor_sync(0xffffffffu, acc[d], 8);
            acc[d] += __shfl_xor_sync(0xffffffffu, acc[d], 4);
            acc[d] += __shfl_xor_sync(0xffffffffu, acc[d], 2);
            acc[d] += __shfl_xor_sync(0xffffffffu, acc[d], 1);
        }
        if (lane == 0) {
#pragma unroll
            for (int d = 0; d < 64; d++) redw[warp * 64 + d] += acc[d];
        }
        __syncthreads();
    }

    if (tid < 64) {
        float t = 0.f;
#pragma unroll
        for (int w = 0; w < 8; w++) t += redw[w * 64 + tid];
        out[(size_t)bh * 64 + tid] = t * (1.f / 784.f);
    }
}

// =====================================================================
extern "C" void kernel_launch(void* const* d_in, const int* in_sizes, int n_in,
                              void* d_out, int out_size)
{
    const float* x      = (const float*)d_in[0];
    const float* w_dwq  = (const float*)d_in[1];
    const float* w_pwq  = (const float*)d_in[2];
    const float* w_dwkv = (const float*)d_in[3];
    const float* w_pwkv = (const float*)d_in[4];
    const float* w_ds   = (const float*)d_in[5];
    const float* ln_g   = (const float*)d_in[6];
    const float* ln_b   = (const float*)d_in[7];
    const float* bnq_g  = (const float*)d_in[8];
    const float* bnq_b  = (const float*)d_in[9];
    const float* bnq_m  = (const float*)d_in[10];
    const float* bnq_v  = (const float*)d_in[11];
    const float* bnkv_g = (const float*)d_in[12];
    const float* bnkv_b = (const float*)d_in[13];
    const float* bnkv_m = (const float*)d_in[14];
    const float* bnkv_v = (const float*)d_in[15];
    const float* bnds_g = (const float*)d_in[16];
    const float* bnds_b = (const float*)d_in[17];
    const float* bnds_m = (const float*)d_in[18];
    const float* bnds_v = (const float*)d_in[19];
    float* out = (float*)d_out;

    float *p_dwq, *p_dwkv, *p_q, *p_kv, *p_res, *p_wq, *p_wkv, *p_wds;
    cudaGetSymbolAddress((void**)&p_dwq,  g_dwq);
    cudaGetSymbolAddress((void**)&p_dwkv, g_dwkv);
    cudaGetSymbolAddress((void**)&p_q,    g_q);
    cudaGetSymbolAddress((void**)&p_kv,   g_kv);
    cudaGetSymbolAddress((void**)&p_res,  g_res);
    cudaGetSymbolAddress((void**)&p_wq,   g_wq);
    cudaGetSymbolAddress((void**)&p_wkv,  g_wkv);
    cudaGetSymbolAddress((void**)&p_wds,  g_wds);

    const int attn_smem = (2 * S2 * 68 + 64 + 64 + 512) * (int)sizeof(float);
    const int gemm_smem = GEMM_SMEM_FLOATS * (int)sizeof(float);  // 53248
    static bool attr_done = false;
    if (!attr_done) {
        cudaFuncSetAttribute(attn_kernel,
                             cudaFuncAttributeMaxDynamicSharedMemorySize, attn_smem);
        cudaFuncSetAttribute(gemm_tc,
                             cudaFuncAttributeMaxDynamicSharedMemorySize, gemm_smem);
        attr_done = true;
    }

    // 0) weight transpose + tf32 rounding
    prep_w<<<(NC * 512  + 255) / 256, 256>>>(w_pwq,  p_wq,  512,  NC, 512);
    prep_w<<<(NC * 1024 + 255) / 256, 256>>>(w_pwkv, p_wkv, 1024, NC, 1024);
    prep_w<<<(NC * 128  + 255) / 256, 256>>>(w_ds,   p_wds, 64,   NC, 128);

    // 1) fused depthwise convs + BN (tf32-rounded output)
    dwconv_fused<<<NB * NC, 256>>>(x, w_dwq, w_dwkv,
                                   bnq_g, bnq_b, bnq_m, bnq_v,
                                   bnkv_g, bnkv_b, bnkv_m, bnkv_v);

    // 2) residual pointwise conv + BN (reads x directly)
    gemm_tc<<<dim3(13, 1, NB), 256, gemm_smem>>>(p_wds, x, p_res, 128, DH, HW,
                                                 bnds_g, bnds_b, bnds_m, bnds_v);

    // 3) q projection
    gemm_tc<<<dim3(13, 4, NB), 256, gemm_smem>>>(p_wq, p_dwq, p_q, 512, INNER, HW,
                                                 nullptr, nullptr, nullptr, nullptr);

    // 4) kv projection
    gemm_tc<<<dim3(4, 8, NB), 256, gemm_smem>>>(p_wkv, p_dwkv, p_kv, 1024, 2 * INNER, S2,
                                                nullptr, nullptr, nullptr, nullptr);

    // 5) fused attention + residual + LN + mean pool
    attn_kernel<<<NB * NHEADS, 256, attn_smem>>>(ln_g, ln_b, out);
}

// round 6
// speedup vs baseline: 3.0032x; 1.7611x over previous
#include <cuda_runtime.h>
#include <math.h>
#include <stdint.h>

#define NB      64
#define NC      640      // K of all GEMMs
#define HW      784      // 28*28
#define S2      196      // 14*14
#define NHEADS  8
#define DH      64
#define INNER   512      // NHEADS*DH
#define EPSF    1e-5f
#define ATTN_SCALE 0.125f
#define SP      204      // padded S-tile row stride

// ---------------- scratch (device globals; no allocation) ----------------
__device__ float g_dwq [NB * NC * HW];       // dwconv(s1)+BN (tf32-rounded)
__device__ float g_dwkv[NB * NC * S2];       // dwconv(s2)+BN (tf32-rounded)
__device__ float g_q   [NB * INNER * HW];    // q  [b][h*64+d][pos], tf32
__device__ float g_kv  [NB * 2 * INNER * S2];// tf32
__device__ float g_res [NB * DH * HW];       // residual [b][d][pos], fp32
__device__ float g_wq  [NC * 512];           // w_pwq^T  [k][m], tf32
__device__ float g_wkv [NC * 1024];          // w_pwkv^T [k][m], tf32
__device__ float g_wds [NC * 128];           // w_ds^T   [k][m], tf32, zero-padded to 128

// ---------------- helpers ----------------
__device__ __forceinline__ float to_tf32(float v) {
    uint32_t r;
    asm("cvt.rna.tf32.f32 %0, %1;" : "=r"(r) : "f"(v));
    return __uint_as_float(r);
}

__device__ __forceinline__ void cp16(uint32_t dst, const void* src, int src_bytes) {
    asm volatile("cp.async.cg.shared.global [%0], [%1], 16, %2;\n"
                 :: "r"(dst), "l"(src), "r"(src_bytes));
}

__device__ __forceinline__ void mma_tf32(float* c, const uint32_t* a, const uint32_t* b) {
    asm volatile(
        "mma.sync.aligned.m16n8k8.row.col.f32.tf32.tf32.f32 "
        "{%0,%1,%2,%3}, {%4,%5,%6,%7}, {%8,%9}, {%0,%1,%2,%3};\n"
        : "+f"(c[0]), "+f"(c[1]), "+f"(c[2]), "+f"(c[3])
        : "r"(a[0]), "r"(a[1]), "r"(a[2]), "r"(a[3]), "r"(b[0]), "r"(b[1]));
}

// =====================================================================
// Weight transpose + tf32 round:  W[M,K] row-major -> out[K][Mpad]
// =====================================================================
__global__ void __launch_bounds__(256)
prep_w(const float* __restrict__ W, float* __restrict__ outp,
       int M, int K, int Mpad)
{
    int idx = blockIdx.x * 256 + threadIdx.x;
    if (idx >= K * Mpad) return;
    int k = idx / Mpad, m = idx - k * Mpad;
    float v = (m < M) ? W[(size_t)m * K + k] : 0.f;
    outp[idx] = to_tf32(v);
}

// =====================================================================
// Fused depthwise conv (stride1 + stride2) + BN, per (b,c) block.
// =====================================================================
__global__ void __launch_bounds__(256)
dwconv_fused(const float* __restrict__ x,
             const float* __restrict__ wq, const float* __restrict__ wkv,
             const float* __restrict__ qg, const float* __restrict__ qb,
             const float* __restrict__ qm, const float* __restrict__ qvv,
             const float* __restrict__ kg, const float* __restrict__ kb,
             const float* __restrict__ km, const float* __restrict__ kvv)
{
    const int bc = blockIdx.x;
    const int c  = bc % NC;
    __shared__ float xs[30 * 30];
    const int tid = threadIdx.x;

    for (int i = tid; i < 900; i += 256) xs[i] = 0.f;
    __syncthreads();
    const float* xp = x + (size_t)bc * HW;
    for (int p = tid; p < HW; p += 256) {
        int yy = p / 28, xx = p % 28;
        xs[(yy + 1) * 30 + xx + 1] = xp[p];
    }
    __syncthreads();

    float wq9[9], wk9[9];
#pragma unroll
    for (int i = 0; i < 9; i++) { wq9[i] = wq[c * 9 + i]; wk9[i] = wkv[c * 9 + i]; }

    const float sq  = qg[c] * rsqrtf(qvv[c] + EPSF);
    const float bq  = qb[c] - qm[c] * sq;
    const float skv = kg[c] * rsqrtf(kvv[c] + EPSF);
    const float bkv = kb[c] - km[c] * skv;

    for (int p = tid; p < HW; p += 256) {
        int oy = p / 28, ox = p % 28;
        const float* s = &xs[oy * 30 + ox];
        float acc = s[0]*wq9[0] + s[1]*wq9[1] + s[2]*wq9[2]
                  + s[30]*wq9[3] + s[31]*wq9[4] + s[32]*wq9[5]
                  + s[60]*wq9[6] + s[61]*wq9[7] + s[62]*wq9[8];
        g_dwq[(size_t)bc * HW + p] = to_tf32(acc * sq + bq);
    }
    for (int p = tid; p < S2; p += 256) {
        int oy = p / 14, ox = p % 14;
        const float* s = &xs[(oy * 2) * 30 + (ox * 2)];
        float acc = s[0]*wk9[0] + s[1]*wk9[1] + s[2]*wk9[2]
                  + s[30]*wk9[3] + s[31]*wk9[4] + s[32]*wk9[5]
                  + s[60]*wk9[6] + s[61]*wk9[7] + s[62]*wk9[8];
        g_dwkv[(size_t)bc * S2 + p] = to_tf32(acc * skv + bkv);
    }
}

// =====================================================================
// tf32 tensor-core GEMM (projections):  C[b](MxN) = wT^T * act[b]
// =====================================================================
#define GEMM_SMEM_FLOATS (2 * (32 * 136 + 32 * 72))
__global__ void __launch_bounds__(256)
gemm_tc(const float* __restrict__ wT, const float* __restrict__ act,
        float* __restrict__ Cc, int Mpad, int M, int N, int round_out,
        const float* __restrict__ bg, const float* __restrict__ bb,
        const float* __restrict__ bm, const float* __restrict__ bv)
{
    extern __shared__ float sm[];
    const int tid  = threadIdx.x;
    const int lane = tid & 31, warp = tid >> 5;
    const int wm = (warp >> 1) * 32;
    const int wn = (warp & 1) * 32;
    const int n0 = blockIdx.x * 64;
    const int m0 = blockIdx.y * 128;
    const float* Ab = act + (size_t)blockIdx.z * NC * N;
    float*       Cb = Cc  + (size_t)blockIdx.z * (size_t)M * N;

    float acc[2][4][4];
#pragma unroll
    for (int i = 0; i < 2; i++)
#pragma unroll
        for (int j = 0; j < 4; j++)
#pragma unroll
            for (int l = 0; l < 4; l++) acc[i][j][l] = 0.f;

    const int a_k = tid >> 5, a_m4 = (tid & 31) * 4;
    const int b_k = tid >> 4, b_n4 = (tid & 15) * 4;

    auto load_tile = [&](int k0, int st) {
        float* As = sm + st * (32 * 136 + 32 * 72);
        float* Bs = As + 32 * 136;
#pragma unroll
        for (int i = 0; i < 4; i++) {
            int k = a_k + i * 8;
            uint32_t dst = (uint32_t)__cvta_generic_to_shared(&As[k * 136 + a_m4]);
            cp16(dst, wT + (size_t)(k0 + k) * Mpad + m0 + a_m4, 16);
        }
#pragma unroll
        for (int i = 0; i < 2; i++) {
            int k = b_k + i * 16;
            int col = n0 + b_n4;
            uint32_t dst = (uint32_t)__cvta_generic_to_shared(&Bs[k * 72 + b_n4]);
            cp16(dst, Ab + (size_t)(k0 + k) * N + col, (col < N) ? 16 : 0);
        }
        asm volatile("cp.async.commit_group;\n");
    };

    load_tile(0, 0);
    for (int t = 0; t < 20; t++) {
        const int st = t & 1;
        if (t < 19) {
            load_tile((t + 1) * 32, st ^ 1);
            asm volatile("cp.async.wait_group 1;\n");
        } else {
            asm volatile("cp.async.wait_group 0;\n");
        }
        __syncthreads();
        const float* As = sm + st * (32 * 136 + 32 * 72);
        const float* Bs = As + 32 * 136;
#pragma unroll
        for (int kk = 0; kk < 32; kk += 8) {
            uint32_t af[2][4], bf[4][2];
            const int kq   = kk + (lane & 3);
            const int mrow = wm + (lane >> 2);
            const int ncol = wn + (lane >> 2);
#pragma unroll
            for (int mt = 0; mt < 2; mt++) {
                af[mt][0] = __float_as_uint(As[kq * 136 + mrow + mt * 16]);
                af[mt][1] = __float_as_uint(As[kq * 136 + mrow + mt * 16 + 8]);
                af[mt][2] = __float_as_uint(As[(kq + 4) * 136 + mrow + mt * 16]);
                af[mt][3] = __float_as_uint(As[(kq + 4) * 136 + mrow + mt * 16 + 8]);
            }
#pragma unroll
            for (int nt = 0; nt < 4; nt++) {
                bf[nt][0] = __float_as_uint(Bs[kq * 72 + ncol + nt * 8]);
                bf[nt][1] = __float_as_uint(Bs[(kq + 4) * 72 + ncol + nt * 8]);
            }
#pragma unroll
            for (int mt = 0; mt < 2; mt++)
#pragma unroll
                for (int nt = 0; nt < 4; nt++)
                    mma_tf32(acc[mt][nt], af[mt], bf[nt]);
        }
        __syncthreads();
    }

    const bool has_bn = (bg != nullptr);
#pragma unroll
    for (int mt = 0; mt < 2; mt++) {
#pragma unroll
        for (int half = 0; half < 2; half++) {
            const int m = m0 + wm + mt * 16 + (lane >> 2) + half * 8;
            if (m >= M) continue;
            float sc = 1.f, bi = 0.f;
            if (has_bn) { sc = bg[m] * rsqrtf(bv[m] + EPSF); bi = bb[m] - bm[m] * sc; }
#pragma unroll
            for (int nt = 0; nt < 4; nt++) {
                const int n = n0 + wn + nt * 8 + 2 * (lane & 3);
                if (n < N) {
                    float2 v;
                    v.x = acc[mt][nt][half * 2 + 0] * sc + bi;
                    v.y = acc[mt][nt][half * 2 + 1] * sc + bi;
                    if (round_out) { v.x = to_tf32(v.x); v.y = to_tf32(v.y); }
                    *(float2*)&Cb[(size_t)m * N + n] = v;
                }
            }
        }
    }
}

// =====================================================================
// Tensor-core attention + residual + LayerNorm + mean pool.
// One block per (b,h); 8 warps, each independently owns 16-row tiles.
// Keys padded 196 -> 200. Per-warp S tile [16][SP] in smem.
// =====================================================================
__global__ void __launch_bounds__(256, 1)
attn_tc(const float* __restrict__ lnw, const float* __restrict__ lnbp,
        float* __restrict__ out)
{
    const int bh = blockIdx.x;
    const int b  = bh >> 3;
    const int h  = bh & 7;

    extern __shared__ __align__(16) float sm[];
    float* ksm  = sm;                    // [200][68]
    float* vsm  = ksm + 200 * 68;        // [200][68]
    float* ssm  = vsm + 200 * 68;        // [8][16*SP]
    float* pool = ssm + 8 * 16 * SP;     // [8][64]
    float* lnsm = pool + 512;            // gamma[64], beta[64]

    const int tid  = threadIdx.x;
    const int lane = tid & 31, warp = tid >> 5;
    const int gid  = lane >> 2, tig = lane & 3;

    // stage K,V transposed: ksm[j][d]
    const float* kg = g_kv + ((size_t)b * 1024 + h * 64) * S2;
    const float* vg = g_kv + ((size_t)b * 1024 + 512 + h * 64) * S2;
    for (int idx = tid; idx < 200 * 64; idx += 256) {
        int j = idx % 200, d = idx / 200;
        ksm[j * 68 + d] = (j < S2) ? kg[(size_t)d * S2 + j] : 0.f;
        vsm[j * 68 + d] = (j < S2) ? vg[(size_t)d * S2 + j] : 0.f;
    }
    if (tid < 128) lnsm[tid] = (tid < 64) ? lnw[h * 64 + tid] : lnbp[h * 64 + tid - 64];
    __syncthreads();

    // per-thread LN params for its 16 d-slots
    float lgr[16], lbr[16];
#pragma unroll
    for (int nt = 0; nt < 8; nt++)
#pragma unroll
        for (int c = 0; c < 2; c++) {
            int d = nt * 8 + 2 * tig + c;
            lgr[nt * 2 + c] = lnsm[d];
            lbr[nt * 2 + c] = lnsm[64 + d];
        }

    float pacc[16];
#pragma unroll
    for (int i = 0; i < 16; i++) pacc[i] = 0.f;

    float* ssw = ssm + warp * 16 * SP;
    const float* qg = g_q + ((size_t)b * INNER + h * 64) * HW;
    const float* rg = g_res + (size_t)b * DH * HW;

    for (int t = warp; t < 49; t += 8) {
        const int r0 = t * 16;

        // ---- Phase A: S = Q K^T (raw, scale applied in softmax) ----
        float sacc[25][4];
#pragma unroll
        for (int nt = 0; nt < 25; nt++) {
            sacc[nt][0] = sacc[nt][1] = sacc[nt][2] = sacc[nt][3] = 0.f;
        }
#pragma unroll
        for (int kk = 0; kk < 8; kk++) {
            const int d0 = kk * 8 + tig;
            uint32_t a[4];
            a[0] = __float_as_uint(qg[(size_t)d0 * HW + r0 + gid]);
            a[1] = __float_as_uint(qg[(size_t)d0 * HW + r0 + gid + 8]);
            a[2] = __float_as_uint(qg[(size_t)(d0 + 4) * HW + r0 + gid]);
            a[3] = __float_as_uint(qg[(size_t)(d0 + 4) * HW + r0 + gid + 8]);
#pragma unroll
            for (int nt = 0; nt < 25; nt++) {
                uint32_t bfr[2];
                bfr[0] = __float_as_uint(ksm[(nt * 8 + gid) * 68 + d0]);
                bfr[1] = __float_as_uint(ksm[(nt * 8 + gid) * 68 + d0 + 4]);
                mma_tf32(sacc[nt], a, bfr);
            }
        }
        // spill S to smem
#pragma unroll
        for (int nt = 0; nt < 25; nt++) {
            const int colb = nt * 8 + 2 * tig;
            ssw[gid * SP + colb]           = sacc[nt][0];
            ssw[gid * SP + colb + 1]       = sacc[nt][1];
            ssw[(gid + 8) * SP + colb]     = sacc[nt][2];
            ssw[(gid + 8) * SP + colb + 1] = sacc[nt][3];
        }
        __syncwarp();

        // ---- softmax: 2 lanes per row, cols split 98/98 ----
        {
            const int row = lane >> 1, half = lane & 1, base = half * 98;
            float* sr = ssw + row * SP;
            float mx = -1e30f;
            for (int c = 0; c < 98; c++) mx = fmaxf(mx, sr[base + c]);
            mx = fmaxf(mx, __shfl_xor_sync(0xffffffffu, mx, 1));
            const float mxs = mx * ATTN_SCALE;
            float sum = 0.f;
            for (int c = 0; c < 98; c++) {
                float e = __expf(fmaf(sr[base + c], ATTN_SCALE, -mxs));
                sr[base + c] = e;
                sum += e;
            }
            sum += __shfl_xor_sync(0xffffffffu, sum, 1);
            const float inv = 1.f / sum;
            for (int c = 0; c < 98; c++) sr[base + c] *= inv;
            if (half == 0) { sr[196] = 0.f; sr[197] = 0.f; sr[198] = 0.f; sr[199] = 0.f; }
        }
        __syncwarp();

        // ---- Phase B: O = P V ----
        float oacc[8][4];
#pragma unroll
        for (int nt = 0; nt < 8; nt++) {
            oacc[nt][0] = oacc[nt][1] = oacc[nt][2] = oacc[nt][3] = 0.f;
        }
        for (int kk = 0; kk < 25; kk++) {
            const int j0 = kk * 8 + tig;
            uint32_t a[4];
            a[0] = __float_as_uint(ssw[gid * SP + j0]);
            a[1] = __float_as_uint(ssw[(gid + 8) * SP + j0]);
            a[2] = __float_as_uint(ssw[gid * SP + j0 + 4]);
            a[3] = __float_as_uint(ssw[(gid + 8) * SP + j0 + 4]);
#pragma unroll
            for (int nt = 0; nt < 8; nt++) {
                uint32_t bfr[2];
                bfr[0] = __float_as_uint(vsm[j0 * 68 + nt * 8 + gid]);
                bfr[1] = __float_as_uint(vsm[(j0 + 4) * 68 + nt * 8 + gid]);
                mma_tf32(oacc[nt], a, bfr);
            }
        }

        // ---- epilogue: residual + LayerNorm + pool accumulate ----
        float vlo[16], vhi[16];
        float slo = 0.f, shi = 0.f;
#pragma unroll
        for (int nt = 0; nt < 8; nt++)
#pragma unroll
            for (int c = 0; c < 2; c++) {
                const int i = nt * 2 + c;
                const int d = nt * 8 + 2 * tig + c;
                vlo[i] = oacc[nt][c]     + rg[(size_t)d * HW + r0 + gid];
                vhi[i] = oacc[nt][2 + c] + rg[(size_t)d * HW + r0 + gid + 8];
                slo += vlo[i]; shi += vhi[i];
            }
        slo += __shfl_xor_sync(0xffffffffu, slo, 1);
        slo += __shfl_xor_sync(0xffffffffu, slo, 2);
        shi += __shfl_xor_sync(0xffffffffu, shi, 1);
        shi += __shfl_xor_sync(0xffffffffu, shi, 2);
        const float mlo = slo * (1.f / 64.f), mhi = shi * (1.f / 64.f);
        float qlo = 0.f, qhi = 0.f;
#pragma unroll
        for (int i = 0; i < 16; i++) {
            float t1 = vlo[i] - mlo; qlo += t1 * t1;
            float t2 = vhi[i] - mhi; qhi += t2 * t2;
        }
        qlo += __shfl_xor_sync(0xffffffffu, qlo, 1);
        qlo += __shfl_xor_sync(0xffffffffu, qlo, 2);
        qhi += __shfl_xor_sync(0xffffffffu, qhi, 1);
        qhi += __shfl_xor_sync(0xffffffffu, qhi, 2);
        const float ilo = 1.f / (sqrtf(qlo * (1.f / 64.f)) + EPSF);
        const float ihi = 1.f / (sqrtf(qhi * (1.f / 64.f)) + EPSF);
#pragma unroll
        for (int i = 0; i < 16; i++) {
            pacc[i] += (vlo[i] - mlo) * ilo * lgr[i] + lbr[i]
                     + (vhi[i] - mhi) * ihi * lgr[i] + lbr[i];
        }
    }

    // pool: reduce over gid (rows) within warp, then across warps via smem
#pragma unroll
    for (int i = 0; i < 16; i++) {
        pacc[i] += __shfl_xor_sync(0xffffffffu, pacc[i], 4);
        pacc[i] += __shfl_xor_sync(0xffffffffu, pacc[i], 8);
        pacc[i] += __shfl_xor_sync(0xffffffffu, pacc[i], 16);
    }
    if (gid == 0) {
#pragma unroll
        for (int nt = 0; nt < 8; nt++)
#pragma unroll
            for (int c = 0; c < 2; c++) {
                const int d = nt * 8 + 2 * tig + c;
                pool[warp * 64 + d] = pacc[nt * 2 + c];
            }
    }
    __syncthreads();
    if (tid < 64) {
        float s = 0.f;
#pragma unroll
        for (int w = 0; w < 8; w++) s += pool[w * 64 + tid];
        out[(size_t)bh * 64 + tid] = s * (1.f / 784.f);
    }
}

// =====================================================================
extern "C" void kernel_launch(void* const* d_in, const int* in_sizes, int n_in,
                              void* d_out, int out_size)
{
    const float* x      = (const float*)d_in[0];
    const float* w_dwq  = (const float*)d_in[1];
    const float* w_pwq  = (const float*)d_in[2];
    const float* w_dwkv = (const float*)d_in[3];
    const float* w_pwkv = (const float*)d_in[4];
    const float* w_ds   = (const float*)d_in[5];
    const float* ln_g   = (const float*)d_in[6];
    const float* ln_b   = (const float*)d_in[7];
    const float* bnq_g  = (const float*)d_in[8];
    const float* bnq_b  = (const float*)d_in[9];
    const float* bnq_m  = (const float*)d_in[10];
    const float* bnq_v  = (const float*)d_in[11];
    const float* bnkv_g = (const float*)d_in[12];
    const float* bnkv_b = (const float*)d_in[13];
    const float* bnkv_m = (const float*)d_in[14];
    const float* bnkv_v = (const float*)d_in[15];
    const float* bnds_g = (const float*)d_in[16];
    const float* bnds_b = (const float*)d_in[17];
    const float* bnds_m = (const float*)d_in[18];
    const float* bnds_v = (const float*)d_in[19];
    float* out = (float*)d_out;

    float *p_dwq, *p_dwkv, *p_q, *p_kv, *p_res, *p_wq, *p_wkv, *p_wds;
    cudaGetSymbolAddress((void**)&p_dwq,  g_dwq);
    cudaGetSymbolAddress((void**)&p_dwkv, g_dwkv);
    cudaGetSymbolAddress((void**)&p_q,    g_q);
    cudaGetSymbolAddress((void**)&p_kv,   g_kv);
    cudaGetSymbolAddress((void**)&p_res,  g_res);
    cudaGetSymbolAddress((void**)&p_wq,   g_wq);
    cudaGetSymbolAddress((void**)&p_wkv,  g_wkv);
    cudaGetSymbolAddress((void**)&p_wds,  g_wds);

    const int attn_smem = (2 * 200 * 68 + 8 * 16 * SP + 512 + 128) * (int)sizeof(float); // 215808
    const int gemm_smem = GEMM_SMEM_FLOATS * (int)sizeof(float);  // 53248
    static bool attr_done = false;
    if (!attr_done) {
        cudaFuncSetAttribute(attn_tc,
                             cudaFuncAttributeMaxDynamicSharedMemorySize, attn_smem);
        cudaFuncSetAttribute(gemm_tc,
                             cudaFuncAttributeMaxDynamicSharedMemorySize, gemm_smem);
        attr_done = true;
    }

    // 0) weight transpose + tf32 rounding
    prep_w<<<(NC * 512  + 255) / 256, 256>>>(w_pwq,  p_wq,  512,  NC, 512);
    prep_w<<<(NC * 1024 + 255) / 256, 256>>>(w_pwkv, p_wkv, 1024, NC, 1024);
    prep_w<<<(NC * 128  + 255) / 256, 256>>>(w_ds,   p_wds, 64,   NC, 128);

    // 1) fused depthwise convs + BN (tf32-rounded output)
    dwconv_fused<<<NB * NC, 256>>>(x, w_dwq, w_dwkv,
                                   bnq_g, bnq_b, bnq_m, bnq_v,
                                   bnkv_g, bnkv_b, bnkv_m, bnkv_v);

    // 2) residual pointwise conv + BN (fp32 output)
    gemm_tc<<<dim3(13, 1, NB), 256, gemm_smem>>>(p_wds, x, p_res, 128, DH, HW, 0,
                                                 bnds_g, bnds_b, bnds_m, bnds_v);

    // 3) q projection (tf32-rounded output)
    gemm_tc<<<dim3(13, 4, NB), 256, gemm_smem>>>(p_wq, p_dwq, p_q, 512, INNER, HW, 1,
                                                 nullptr, nullptr, nullptr, nullptr);

    // 4) kv projection (tf32-rounded output)
    gemm_tc<<<dim3(4, 8, NB), 256, gemm_smem>>>(p_wkv, p_dwkv, p_kv, 1024, 2 * INNER, S2, 1,
                                                nullptr, nullptr, nullptr, nullptr);

    // 5) tensor-core attention + residual + LN + mean pool
    attn_tc<<<NB * NHEADS, 256, attn_smem>>>(ln_g, ln_b, out);
}

// round 8
// speedup vs baseline: 3.1185x; 1.0384x over previous
#include <cuda_runtime.h>
#include <math.h>
#include <stdint.h>

#define NB      64
#define NC      640      // K of all GEMMs
#define HW      784      // 28*28
#define S2      196      // 14*14
#define NHEADS  8
#define DH      64
#define INNER   512      // NHEADS*DH
#define EPSF    1e-5f
#define ATTN_SCALE 0.125f

// ---------------- scratch (device globals; no allocation) ----------------
__device__ float g_dwq [NB * NC * HW];       // dwconv(s1)+BN (tf32-rounded)
__device__ float g_dwkv[NB * NC * S2];       // dwconv(s2)+BN (tf32-rounded)
__device__ float g_q   [NB * INNER * HW];    // q  [b][h*64+d][pos], tf32
__device__ float g_kv  [NB * 2 * INNER * S2];// tf32
__device__ float g_res [NB * DH * HW];       // residual [b][d][pos], fp32
__device__ float g_wq  [NC * 512];           // w_pwq^T  [k][m], tf32
__device__ float g_wkv [NC * 1024];          // w_pwkv^T [k][m], tf32
__device__ float g_wds [NC * 128];           // w_ds^T   [k][m], tf32, zero-padded to 128

// ---------------- helpers ----------------
__device__ __forceinline__ float to_tf32(float v) {
    uint32_t r;
    asm("cvt.rna.tf32.f32 %0, %1;" : "=r"(r) : "f"(v));
    return __uint_as_float(r);
}

__device__ __forceinline__ void cp16(uint32_t dst, const void* src, int src_bytes) {
    asm volatile("cp.async.cg.shared.global [%0], [%1], 16, %2;\n"
                 :: "r"(dst), "l"(src), "r"(src_bytes));
}

__device__ __forceinline__ void mma_tf32(float* c, const uint32_t* a, const uint32_t* b) {
    asm volatile(
        "mma.sync.aligned.m16n8k8.row.col.f32.tf32.tf32.f32 "
        "{%0,%1,%2,%3}, {%4,%5,%6,%7}, {%8,%9}, {%0,%1,%2,%3};\n"
        : "+f"(c[0]), "+f"(c[1]), "+f"(c[2]), "+f"(c[3])
        : "r"(a[0]), "r"(a[1]), "r"(a[2]), "r"(a[3]), "r"(b[0]), "r"(b[1]));
}

// =====================================================================
// Single prep kernel: transpose + tf32-round all three weight matrices.
// =====================================================================
#define PREP_Q_SZ   (NC * 512)
#define PREP_KV_SZ  (NC * 1024)
#define PREP_DS_SZ  (NC * 128)
__global__ void __launch_bounds__(256)
prep_all(const float* __restrict__ wq, const float* __restrict__ wkv,
         const float* __restrict__ wds)
{
    int idx = blockIdx.x * 256 + threadIdx.x;
    if (idx < PREP_Q_SZ) {
        int k = idx / 512, m = idx - k * 512;
        g_wq[idx] = to_tf32(wq[(size_t)m * NC + k]);
    } else if (idx < PREP_Q_SZ + PREP_KV_SZ) {
        int i = idx - PREP_Q_SZ;
        int k = i / 1024, m = i - k * 1024;
        g_wkv[i] = to_tf32(wkv[(size_t)m * NC + k]);
    } else if (idx < PREP_Q_SZ + PREP_KV_SZ + PREP_DS_SZ) {
        int i = idx - PREP_Q_SZ - PREP_KV_SZ;
        int k = i / 128, m = i - k * 128;
        g_wds[i] = (m < 64) ? to_tf32(wds[(size_t)m * NC + k]) : 0.f;
    }
}

// =====================================================================
// Fused depthwise conv (stride1 + stride2) + BN, per (b,c) block.
// 2D thread mapping: lane = column, warp row-strided — no div/mod.
// =====================================================================
__global__ void __launch_bounds__(256)
dwconv_fused(const float* __restrict__ x,
             const float* __restrict__ wq, const float* __restrict__ wkv,
             const float* __restrict__ qg, const float* __restrict__ qb,
             const float* __restrict__ qm, const float* __restrict__ qvv,
             const float* __restrict__ kg, const float* __restrict__ kb,
             const float* __restrict__ km, const float* __restrict__ kvv)
{
    const int bc = blockIdx.x;
    const int c  = bc % NC;
    __shared__ float xs[30 * 30];
    const int tid = threadIdx.x;
    const int cx = tid & 31, ry = tid >> 5;   // col lane, row stride 8

    for (int i = tid; i < 900; i += 256) xs[i] = 0.f;
    __syncthreads();
    const float* xp = x + (size_t)bc * HW;
    if (cx < 28) {
        for (int r = ry; r < 28; r += 8)
            xs[(r + 1) * 30 + cx + 1] = xp[r * 28 + cx];
    }
    __syncthreads();

    float wq9[9], wk9[9];
#pragma unroll
    for (int i = 0; i < 9; i++) { wq9[i] = wq[c * 9 + i]; wk9[i] = wkv[c * 9 + i]; }

    const float sq  = qg[c] * rsqrtf(qvv[c] + EPSF);
    const float bq  = qb[c] - qm[c] * sq;
    const float skv = kg[c] * rsqrtf(kvv[c] + EPSF);
    const float bkv = kb[c] - km[c] * skv;

    if (cx < 28) {
        float* oq = g_dwq + (size_t)bc * HW;
        for (int r = ry; r < 28; r += 8) {
            const float* s = &xs[r * 30 + cx];
            float acc = s[0]*wq9[0] + s[1]*wq9[1] + s[2]*wq9[2]
                      + s[30]*wq9[3] + s[31]*wq9[4] + s[32]*wq9[5]
                      + s[60]*wq9[6] + s[61]*wq9[7] + s[62]*wq9[8];
            oq[r * 28 + cx] = to_tf32(acc * sq + bq);
        }
    }
    if (cx < 14) {
        float* okv = g_dwkv + (size_t)bc * S2;
        for (int r = ry; r < 14; r += 8) {
            const float* s = &xs[(r * 2) * 30 + cx * 2];
            float acc = s[0]*wk9[0] + s[1]*wk9[1] + s[2]*wk9[2]
                      + s[30]*wk9[3] + s[31]*wk9[4] + s[32]*wk9[5]
                      + s[60]*wk9[6] + s[61]*wk9[7] + s[62]*wk9[8];
            okv[r * 14 + cx] = to_tf32(acc * skv + bkv);
        }
    }
}

// =====================================================================
// tf32 tensor-core GEMM (projections):  C[b](MxN) = wT^T * act[b]
// =====================================================================
#define GEMM_SMEM_FLOATS (2 * (32 * 136 + 32 * 72))
__global__ void __launch_bounds__(256)
gemm_tc(const float* __restrict__ wT, const float* __restrict__ act,
        float* __restrict__ Cc, int Mpad, int M, int N, int round_out,
        const float* __restrict__ bg, const float* __restrict__ bb,
        const float* __restrict__ bm, const float* __restrict__ bv)
{
    extern __shared__ float sm[];
    const int tid  = threadIdx.x;
    const int lane = tid & 31, warp = tid >> 5;
    const int wm = (warp >> 1) * 32;
    const int wn = (warp & 1) * 32;
    const int n0 = blockIdx.x * 64;
    const int m0 = blockIdx.y * 128;
    const float* Ab = act + (size_t)blockIdx.z * NC * N;
    float*       Cb = Cc  + (size_t)blockIdx.z * (size_t)M * N;

    float acc[2][4][4];
#pragma unroll
    for (int i = 0; i < 2; i++)
#pragma unroll
        for (int j = 0; j < 4; j++)
#pragma unroll
            for (int l = 0; l < 4; l++) acc[i][j][l] = 0.f;

    const int a_k = tid >> 5, a_m4 = (tid & 31) * 4;
    const int b_k = tid >> 4, b_n4 = (tid & 15) * 4;

    auto load_tile = [&](int k0, int st) {
        float* As = sm + st * (32 * 136 + 32 * 72);
        float* Bs = As + 32 * 136;
#pragma unroll
        for (int i = 0; i < 4; i++) {
            int k = a_k + i * 8;
            uint32_t dst = (uint32_t)__cvta_generic_to_shared(&As[k * 136 + a_m4]);
            cp16(dst, wT + (size_t)(k0 + k) * Mpad + m0 + a_m4, 16);
        }
#pragma unroll
        for (int i = 0; i < 2; i++) {
            int k = b_k + i * 16;
            int col = n0 + b_n4;
            uint32_t dst = (uint32_t)__cvta_generic_to_shared(&Bs[k * 72 + b_n4]);
            cp16(dst, Ab + (size_t)(k0 + k) * N + col, (col < N) ? 16 : 0);
        }
        asm volatile("cp.async.commit_group;\n");
    };

    load_tile(0, 0);
    for (int t = 0; t < 20; t++) {
        const int st = t & 1;
        if (t < 19) {
            load_tile((t + 1) * 32, st ^ 1);
            asm volatile("cp.async.wait_group 1;\n");
        } else {
            asm volatile("cp.async.wait_group 0;\n");
        }
        __syncthreads();
        const float* As = sm + st * (32 * 136 + 32 * 72);
        const float* Bs = As + 32 * 136;
#pragma unroll
        for (int kk = 0; kk < 32; kk += 8) {
            uint32_t af[2][4], bf[4][2];
            const int kq   = kk + (lane & 3);
            const int mrow = wm + (lane >> 2);
            const int ncol = wn + (lane >> 2);
#pragma unroll
            for (int mt = 0; mt < 2; mt++) {
                af[mt][0] = __float_as_uint(As[kq * 136 + mrow + mt * 16]);
                af[mt][1] = __float_as_uint(As[kq * 136 + mrow + mt * 16 + 8]);
                af[mt][2] = __float_as_uint(As[(kq + 4) * 136 + mrow + mt * 16]);
                af[mt][3] = __float_as_uint(As[(kq + 4) * 136 + mrow + mt * 16 + 8]);
            }
#pragma unroll
            for (int nt = 0; nt < 4; nt++) {
                bf[nt][0] = __float_as_uint(Bs[kq * 72 + ncol + nt * 8]);
                bf[nt][1] = __float_as_uint(Bs[(kq + 4) * 72 + ncol + nt * 8]);
            }
#pragma unroll
            for (int mt = 0; mt < 2; mt++)
#pragma unroll
                for (int nt = 0; nt < 4; nt++)
                    mma_tf32(acc[mt][nt], af[mt], bf[nt]);
        }
        __syncthreads();
    }

    const bool has_bn = (bg != nullptr);
#pragma unroll
    for (int mt = 0; mt < 2; mt++) {
#pragma unroll
        for (int half = 0; half < 2; half++) {
            const int m = m0 + wm + mt * 16 + (lane >> 2) + half * 8;
            if (m >= M) continue;
            float sc = 1.f, bi = 0.f;
            if (has_bn) { sc = bg[m] * rsqrtf(bv[m] + EPSF); bi = bb[m] - bm[m] * sc; }
#pragma unroll
            for (int nt = 0; nt < 4; nt++) {
                const int n = n0 + wn + nt * 8 + 2 * (lane & 3);
                if (n < N) {
                    float2 v;
                    v.x = acc[mt][nt][half * 2 + 0] * sc + bi;
                    v.y = acc[mt][nt][half * 2 + 1] * sc + bi;
                    if (round_out) { v.x = to_tf32(v.x); v.y = to_tf32(v.y); }
                    *(float2*)&Cb[(size_t)m * N + n] = v;
                }
            }
        }
    }
}

// =====================================================================
// Tensor-core attention, register-resident softmax (no S smem).
// One block per (b,h); 8 warps, each owns 16-row tiles (49 tiles).
// P C-fragments converted to A-fragments via intra-quad shuffles.
// =====================================================================
__global__ void __launch_bounds__(256)
attn_tc(const float* __restrict__ lnw, const float* __restrict__ lnbp,
        float* __restrict__ out)
{
    const int bh = blockIdx.x;
    const int b  = bh >> 3;
    const int h  = bh & 7;

    extern __shared__ __align__(16) float sm[];
    float* ksm  = sm;                    // [200][68]
    float* vsm  = ksm + 200 * 68;        // [200][68]
    float* pool = vsm + 200 * 68;        // [8][64]
    float* lnsm = pool + 512;            // gamma[64], beta[64]

    const int tid  = threadIdx.x;
    const int lane = tid & 31, warp = tid >> 5;
    const int gid  = lane >> 2, tig = lane & 3;

    // stage K,V transposed: ksm[j][d], keys padded 196->200 with zeros
    const float* kg = g_kv + ((size_t)b * 1024 + h * 64) * S2;
    const float* vg = g_kv + ((size_t)b * 1024 + 512 + h * 64) * S2;
    for (int idx = tid; idx < 200 * 64; idx += 256) {
        int j = idx % 200, d = idx / 200;
        ksm[j * 68 + d] = (j < S2) ? kg[(size_t)d * S2 + j] : 0.f;
        vsm[j * 68 + d] = (j < S2) ? vg[(size_t)d * S2 + j] : 0.f;
    }
    if (tid < 128) lnsm[tid] = (tid < 64) ? lnw[h * 64 + tid] : lnbp[h * 64 + tid - 64];
    __syncthreads();

    float pacc[16];
#pragma unroll
    for (int i = 0; i < 16; i++) pacc[i] = 0.f;

    const float* qg = g_q + ((size_t)b * INNER + h * 64) * HW;
    const float* rg = g_res + (size_t)b * DH * HW;

    const int srcLow  = (lane & ~3) | (tig >> 1);
    const int srcHigh = srcLow + 2;
    const bool odd = (tig & 1) != 0;

    for (int t = warp; t < 49; t += 8) {
        const int r0 = t * 16;

        // ---- Phase A: S = Q K^T ----
        float sacc[25][4];
#pragma unroll
        for (int nt = 0; nt < 25; nt++) {
            sacc[nt][0] = sacc[nt][1] = sacc[nt][2] = sacc[nt][3] = 0.f;
        }
#pragma unroll
        for (int kk = 0; kk < 8; kk++) {
            const int d0 = kk * 8 + tig;
            uint32_t a[4];
            a[0] = __float_as_uint(qg[(size_t)d0 * HW + r0 + gid]);
            a[1] = __float_as_uint(qg[(size_t)d0 * HW + r0 + gid + 8]);
            a[2] = __float_as_uint(qg[(size_t)(d0 + 4) * HW + r0 + gid]);
            a[3] = __float_as_uint(qg[(size_t)(d0 + 4) * HW + r0 + gid + 8]);
#pragma unroll
            for (int nt = 0; nt < 25; nt++) {
                uint32_t bfr[2];
                bfr[0] = __float_as_uint(ksm[(nt * 8 + gid) * 68 + d0]);
                bfr[1] = __float_as_uint(ksm[(nt * 8 + gid) * 68 + d0 + 4]);
                mma_tf32(sacc[nt], a, bfr);
            }
        }
        // mask padded cols (tile 24: cols 192 + 2*tig(+1); >=196 <=> tig>=2)
        if (tig >= 2) {
            sacc[24][0] = sacc[24][1] = sacc[24][2] = sacc[24][3] = -1e30f;
        }

        // ---- softmax in registers (rows gid / gid+8, quad reduce) ----
        float mlo = -1e30f, mhi = -1e30f;
#pragma unroll
        for (int nt = 0; nt < 25; nt++) {
            mlo = fmaxf(mlo, fmaxf(sacc[nt][0], sacc[nt][1]));
            mhi = fmaxf(mhi, fmaxf(sacc[nt][2], sacc[nt][3]));
        }
        mlo = fmaxf(mlo, __shfl_xor_sync(0xffffffffu, mlo, 1));
        mlo = fmaxf(mlo, __shfl_xor_sync(0xffffffffu, mlo, 2));
        mhi = fmaxf(mhi, __shfl_xor_sync(0xffffffffu, mhi, 1));
        mhi = fmaxf(mhi, __shfl_xor_sync(0xffffffffu, mhi, 2));
        const float mls = mlo * ATTN_SCALE, mhs = mhi * ATTN_SCALE;
        float slo = 0.f, shi = 0.f;
#pragma unroll
        for (int nt = 0; nt < 25; nt++) {
            float e0 = __expf(fmaf(sacc[nt][0], ATTN_SCALE, -mls));
            float e1 = __expf(fmaf(sacc[nt][1], ATTN_SCALE, -mls));
            float e2 = __expf(fmaf(sacc[nt][2], ATTN_SCALE, -mhs));
            float e3 = __expf(fmaf(sacc[nt][3], ATTN_SCALE, -mhs));
            sacc[nt][0] = e0; sacc[nt][1] = e1; sacc[nt][2] = e2; sacc[nt][3] = e3;
            slo += e0 + e1; shi += e2 + e3;
        }
        slo += __shfl_xor_sync(0xffffffffu, slo, 1);
        slo += __shfl_xor_sync(0xffffffffu, slo, 2);
        shi += __shfl_xor_sync(0xffffffffu, shi, 1);
        shi += __shfl_xor_sync(0xffffffffu, shi, 2);
        const float rlo = 1.f / slo, rhi = 1.f / shi;
#pragma unroll
        for (int nt = 0; nt < 25; nt++) {
            sacc[nt][0] *= rlo; sacc[nt][1] *= rlo;
            sacc[nt][2] *= rhi; sacc[nt][3] *= rhi;
        }

        // ---- Phase B: O = P V (C-frag -> A-frag via quad shuffles) ----
        float oacc[8][4];
#pragma unroll
        for (int nt = 0; nt < 8; nt++) {
            oacc[nt][0] = oacc[nt][1] = oacc[nt][2] = oacc[nt][3] = 0.f;
        }
#pragma unroll
        for (int kk = 0; kk < 25; kk++) {
            float u0 = __shfl_sync(0xffffffffu, sacc[kk][0], srcLow);
            float u1 = __shfl_sync(0xffffffffu, sacc[kk][1], srcLow);
            float w0 = __shfl_sync(0xffffffffu, sacc[kk][2], srcLow);
            float w1 = __shfl_sync(0xffffffffu, sacc[kk][3], srcLow);
            float v0 = __shfl_sync(0xffffffffu, sacc[kk][0], srcHigh);
            float v1 = __shfl_sync(0xffffffffu, sacc[kk][1], srcHigh);
            float z0 = __shfl_sync(0xffffffffu, sacc[kk][2], srcHigh);
            float z1 = __shfl_sync(0xffffffffu, sacc[kk][3], srcHigh);
            uint32_t a[4];
            a[0] = __float_as_uint(odd ? u1 : u0);   // P[gid][k0+tig]
            a[1] = __float_as_uint(odd ? w1 : w0);   // P[gid+8][k0+tig]
            a[2] = __float_as_uint(odd ? v1 : v0);   // P[gid][k0+tig+4]
            a[3] = __float_as_uint(odd ? z1 : z0);   // P[gid+8][k0+tig+4]
            const int j0 = kk * 8 + tig;
#pragma unroll
            for (int nt = 0; nt < 8; nt++) {
                uint32_t bfr[2];
                bfr[0] = __float_as_uint(vsm[j0 * 68 + nt * 8 + gid]);
                bfr[1] = __float_as_uint(vsm[(j0 + 4) * 68 + nt * 8 + gid]);
                mma_tf32(oacc[nt], a, bfr);
            }
        }

        // ---- epilogue: residual + LayerNorm + pool accumulate ----
        float vlo[16], vhi[16];
        float slo2 = 0.f, shi2 = 0.f;
#pragma unroll
        for (int nt = 0; nt < 8; nt++)
#pragma unroll
            for (int c = 0; c < 2; c++) {
                const int i = nt * 2 + c;
                const int d = nt * 8 + 2 * tig + c;
                vlo[i] = oacc[nt][c]     + rg[(size_t)d * HW + r0 + gid];
                vhi[i] = oacc[nt][2 + c] + rg[(size_t)d * HW + r0 + gid + 8];
                slo2 += vlo[i]; shi2 += vhi[i];
            }
        slo2 += __shfl_xor_sync(0xffffffffu, slo2, 1);
        slo2 += __shfl_xor_sync(0xffffffffu, slo2, 2);
        shi2 += __shfl_xor_sync(0xffffffffu, shi2, 1);
        shi2 += __shfl_xor_sync(0xffffffffu, shi2, 2);
        const float mlo2 = slo2 * (1.f / 64.f), mhi2 = shi2 * (1.f / 64.f);
        float qlo = 0.f, qhi = 0.f;
#pragma unroll
        for (int i = 0; i < 16; i++) {
            float t1 = vlo[i] - mlo2; qlo += t1 * t1;
            float t2 = vhi[i] - mhi2; qhi += t2 * t2;
        }
        qlo += __shfl_xor_sync(0xffffffffu, qlo, 1);
        qlo += __shfl_xor_sync(0xffffffffu, qlo, 2);
        qhi += __shfl_xor_sync(0xffffffffu, qhi, 1);
        qhi += __shfl_xor_sync(0xffffffffu, qhi, 2);
        const float ilo = 1.f / (sqrtf(qlo * (1.f / 64.f)) + EPSF);
        const float ihi = 1.f / (sqrtf(qhi * (1.f / 64.f)) + EPSF);
#pragma unroll
        for (int nt = 0; nt < 8; nt++)
#pragma unroll
            for (int c = 0; c < 2; c++) {
                const int i = nt * 2 + c;
                const int d = nt * 8 + 2 * tig + c;
                const float lg = lnsm[d], lb = lnsm[64 + d];
                pacc[i] += (vlo[i] - mlo2) * ilo * lg + lb
                         + (vhi[i] - mhi2) * ihi * lg + lb;
            }
    }

    // pool: reduce over gid within warp, then across warps via smem
#pragma unroll
    for (int i = 0; i < 16; i++) {
        pacc[i] += __shfl_xor_sync(0xffffffffu, pacc[i], 4);
        pacc[i] += __shfl_xor_sync(0xffffffffu, pacc[i], 8);
        pacc[i] += __shfl_xor_sync(0xffffffffu, pacc[i], 16);
    }
    if (gid == 0) {
#pragma unroll
        for (int nt = 0; nt < 8; nt++)
#pragma unroll
            for (int c = 0; c < 2; c++) {
                const int d = nt * 8 + 2 * tig + c;
                pool[warp * 64 + d] = pacc[nt * 2 + c];
            }
    }
    __syncthreads();
    if (tid < 64) {
        float s = 0.f;
#pragma unroll
        for (int w = 0; w < 8; w++) s += pool[w * 64 + tid];
        out[(size_t)bh * 64 + tid] = s * (1.f / 784.f);
    }
}

// =====================================================================
extern "C" void kernel_launch(void* const* d_in, const int* in_sizes, int n_in,
                              void* d_out, int out_size)
{
    const float* x      = (const float*)d_in[0];
    const float* w_dwq  = (const float*)d_in[1];
    const float* w_pwq  = (const float*)d_in[2];
    const float* w_dwkv = (const float*)d_in[3];
    const float* w_pwkv = (const float*)d_in[4];
    const float* w_ds   = (const float*)d_in[5];
    const float* ln_g   = (const float*)d_in[6];
    const float* ln_b   = (const float*)d_in[7];
    const float* bnq_g  = (const float*)d_in[8];
    const float* bnq_b  = (const float*)d_in[9];
    const float* bnq_m  = (const float*)d_in[10];
    const float* bnq_v  = (const float*)d_in[11];
    const float* bnkv_g = (const float*)d_in[12];
    const float* bnkv_b = (const float*)d_in[13];
    const float* bnkv_m = (const float*)d_in[14];
    const float* bnkv_v = (const float*)d_in[15];
    const float* bnds_g = (const float*)d_in[16];
    const float* bnds_b = (const float*)d_in[17];
    const float* bnds_m = (const float*)d_in[18];
    const float* bnds_v = (const float*)d_in[19];
    float* out = (float*)d_out;

    float *p_dwq, *p_dwkv, *p_q, *p_kv, *p_res, *p_wq, *p_wkv, *p_wds;
    cudaGetSymbolAddress((void**)&p_dwq,  g_dwq);
    cudaGetSymbolAddress((void**)&p_dwkv, g_dwkv);
    cudaGetSymbolAddress((void**)&p_q,    g_q);
    cudaGetSymbolAddress((void**)&p_kv,   g_kv);
    cudaGetSymbolAddress((void**)&p_res,  g_res);
    cudaGetSymbolAddress((void**)&p_wq,   g_wq);
    cudaGetSymbolAddress((void**)&p_wkv,  g_wkv);
    cudaGetSymbolAddress((void**)&p_wds,  g_wds);

    const int attn_smem = (2 * 200 * 68 + 512 + 128) * (int)sizeof(float); // 111360
    const int gemm_smem = GEMM_SMEM_FLOATS * (int)sizeof(float);           // 53248
    static bool attr_done = false;
    if (!attr_done) {
        cudaFuncSetAttribute(attn_tc,
                             cudaFuncAttributeMaxDynamicSharedMemorySize, attn_smem);
        cudaFuncSetAttribute(gemm_tc,
                             cudaFuncAttributeMaxDynamicSharedMemorySize, gemm_smem);
        attr_done = true;
    }

    // 0) weight transpose + tf32 rounding (single kernel)
    const int prep_total = PREP_Q_SZ + PREP_KV_SZ + PREP_DS_SZ;
    prep_all<<<(prep_total + 255) / 256, 256>>>(w_pwq, w_pwkv, w_ds);

    // 1) fused depthwise convs + BN (tf32-rounded output)
    dwconv_fused<<<NB * NC, 256>>>(x, w_dwq, w_dwkv,
                                   bnq_g, bnq_b, bnq_m, bnq_v,
                                   bnkv_g, bnkv_b, bnkv_m, bnkv_v);

    // 2) residual pointwise conv + BN (fp32 output)
    gemm_tc<<<dim3(13, 1, NB), 256, gemm_smem>>>(p_wds, x, p_res, 128, DH, HW, 0,
                                                 bnds_g, bnds_b, bnds_m, bnds_v);

    // 3) q projection (tf32-rounded output)
    gemm_tc<<<dim3(13, 4, NB), 256, gemm_smem>>>(p_wq, p_dwq, p_q, 512, INNER, HW, 1,
                                                 nullptr, nullptr, nullptr, nullptr);

    // 4) kv projection (tf32-rounded output)
    gemm_tc<<<dim3(4, 8, NB), 256, gemm_smem>>>(p_wkv, p_dwkv, p_kv, 1024, 2 * INNER, S2, 1,
                                                nullptr, nullptr, nullptr, nullptr);

    // 5) tensor-core attention + residual + LN + mean pool
    attn_tc<<<NB * NHEADS, 256, attn_smem>>>(ln_g, ln_b, out);
}